// round 2
// baseline (speedup 1.0000x reference)
#include <cuda_runtime.h>
#include <math.h>

// Shapes are fixed by the dataset.
#define SB 2048
#define BB 2
#define HH 8
#define HD 128
#define DD 1024

// Scratch (static device globals: allowed; no runtime allocation).
__device__ float g_recip[(size_t)SB * SB];        // 16 MB: 1/(dist^2 + eps)
__device__ float g_masses[BB * HH * SB];          // (b,h,s)
__device__ float g_v[(size_t)BB * SB * DD];       // v = x @ v_w^T, (B,S,D)
__device__ float g_ho[(size_t)BB * SB * DD];      // head_out, (B,S,D)

// FMA-only exp for f in [0, 50]. Avoids MUFU throughput wall (67M exps).
// e^f = 2^(f*log2e); split t = n + r, r in [-0.5, 0.5]; 2^r via deg-6 Taylor.
__device__ __forceinline__ float fast_exp_pos(float f) {
    float t = f * 1.44269504088896340736f;
    float z = t + 12582912.0f;            // round-to-nearest int (n in [0,73])
    float n = z - 12582912.0f;
    float r = t - n;
    float p = 1.5403530e-4f;
    p = fmaf(p, r, 1.3333558e-3f);
    p = fmaf(p, r, 9.6181291e-3f);
    p = fmaf(p, r, 5.5504109e-2f);
    p = fmaf(p, r, 2.4022651e-1f);
    p = fmaf(p, r, 6.9314718e-1f);
    p = fmaf(p, r, 1.0f);
    int e = (int)n;
    return p * __int_as_float((e + 127) << 23);
}

// ---------------------------------------------------------------------------
// Kernel 1: recip[q,k] = 1 / (dist(q,k)^2 + 1e-6), warped distance.
// ---------------------------------------------------------------------------
__global__ void k_recip(const float* __restrict__ pos) {
    int idx = blockIdx.x * blockDim.x + threadIdx.x;   // S*S = 4M threads
    int q = idx >> 11;
    int k = idx & (SB - 1);
    float4 q0 = *(const float4*)(pos + q * 8);
    float4 q1 = *(const float4*)(pos + q * 8 + 4);
    float4 k0 = *(const float4*)(pos + k * 8);
    float4 k1 = *(const float4*)(pos + k * 8 + 4);
    float d2 = 1e-12f;
    float df;
    df = q0.x - k0.x; d2 = fmaf(df, df, d2);
    df = q0.y - k0.y; d2 = fmaf(df, df, d2);
    df = q0.z - k0.z; d2 = fmaf(df, df, d2);
    df = q0.w - k0.w; d2 = fmaf(df, df, d2);
    df = q1.x - k1.x; d2 = fmaf(df, df, d2);
    df = q1.y - k1.y; d2 = fmaf(df, df, d2);
    df = q1.z - k1.z; d2 = fmaf(df, df, d2);
    df = q1.w - k1.w; d2 = fmaf(df, df, d2);
    float dist = sqrtf(d2);
    dist = dist * (1.0f + 0.15f * sinf(dist));
    dist = fmaxf(dist, 0.0f);
    g_recip[idx] = 1.0f / (dist * dist + 1e-6f);
}

// ---------------------------------------------------------------------------
// Kernel 2: masses[b,h,s] = sigmoid(dot(x[b,s,h*128:+128], mass_w[h])).
// One warp per (b,h,s).
// ---------------------------------------------------------------------------
__global__ void k_masses(const float* __restrict__ x, const float* __restrict__ mw) {
    int g = blockIdx.x * 8 + (threadIdx.x >> 5);   // 0 .. B*H*S-1
    int lane = threadIdx.x & 31;
    int b = g >> 14;          // H*S = 16384
    int h = (g >> 11) & 7;
    int s = g & 2047;
    const float* xr = x + ((size_t)b * SB + s) * DD + h * HD;
    const float* wr = mw + h * HD;
    float sum = 0.f;
#pragma unroll
    for (int i = 0; i < 4; i++)
        sum = fmaf(xr[lane + 32 * i], wr[lane + 32 * i], sum);
#pragma unroll
    for (int o = 16; o; o >>= 1)
        sum += __shfl_xor_sync(0xffffffffu, sum, o);
    if (lane == 0)
        g_masses[g] = 1.0f / (1.0f + __expf(-sum));
}

// ---------------------------------------------------------------------------
// Kernels 3 & 5: C[m,n] = sum_k A[m,k] * Bw[n,k]  (NT GEMM, all row-major).
// M=4096, N=K=1024. 128x128 tile, 256 threads, 8x8 micro-tile.
// Double-buffered smem: one __syncthreads per K-tile, loads overlap compute.
// mode 0: A = Ain (x),  C = g_v
// mode 1: A = g_ho,     C = Cext (harness d_out)
// ---------------------------------------------------------------------------
__global__ __launch_bounds__(256) void k_gemm_nt(const float* __restrict__ Ain,
                                                 const float* __restrict__ Bw,
                                                 float* __restrict__ Cext,
                                                 int mode) {
    const float* A = (mode == 0) ? Ain : g_ho;
    float* C = (mode == 0) ? g_v : Cext;
    const int K = DD, N = DD;

    __shared__ float As[2][16 * 128];   // [buf][kk][m]
    __shared__ float Bs[2][16 * 128];   // [buf][kk][n]

    int tid = threadIdx.x;
    int tx = tid & 15, ty = tid >> 4;
    int mbase = blockIdx.y * 128, nbase = blockIdx.x * 128;

    // Per-thread fixed load coordinates: 512 float4s per operand per tile,
    // 2 per thread.
    int row0 = (tid * 2) >> 2, seg0 = (tid * 2) & 3;          // even float4
    int row1 = (tid * 2 + 1) >> 2, seg1 = (tid * 2 + 1) & 3;  // odd  float4

    float acc[8][8];
#pragma unroll
    for (int i = 0; i < 8; i++)
#pragma unroll
        for (int j = 0; j < 8; j++) acc[i][j] = 0.f;

    // Prologue: load tile kb=0 into buffer 0.
    {
        float4 av0 = *(const float4*)(A + (size_t)(mbase + row0) * K + seg0 * 4);
        float4 av1 = *(const float4*)(A + (size_t)(mbase + row1) * K + seg1 * 4);
        float4 bv0 = *(const float4*)(Bw + (size_t)(nbase + row0) * K + seg0 * 4);
        float4 bv1 = *(const float4*)(Bw + (size_t)(nbase + row1) * K + seg1 * 4);
        As[0][(seg0 * 4 + 0) * 128 + row0] = av0.x;
        As[0][(seg0 * 4 + 1) * 128 + row0] = av0.y;
        As[0][(seg0 * 4 + 2) * 128 + row0] = av0.z;
        As[0][(seg0 * 4 + 3) * 128 + row0] = av0.w;
        As[0][(seg1 * 4 + 0) * 128 + row1] = av1.x;
        As[0][(seg1 * 4 + 1) * 128 + row1] = av1.y;
        As[0][(seg1 * 4 + 2) * 128 + row1] = av1.z;
        As[0][(seg1 * 4 + 3) * 128 + row1] = av1.w;
        Bs[0][(seg0 * 4 + 0) * 128 + row0] = bv0.x;
        Bs[0][(seg0 * 4 + 1) * 128 + row0] = bv0.y;
        Bs[0][(seg0 * 4 + 2) * 128 + row0] = bv0.z;
        Bs[0][(seg0 * 4 + 3) * 128 + row0] = bv0.w;
        Bs[0][(seg1 * 4 + 0) * 128 + row1] = bv1.x;
        Bs[0][(seg1 * 4 + 1) * 128 + row1] = bv1.y;
        Bs[0][(seg1 * 4 + 2) * 128 + row1] = bv1.z;
        Bs[0][(seg1 * 4 + 3) * 128 + row1] = bv1.w;
    }
    __syncthreads();

    int buf = 0;
    for (int kb = 0; kb < K; kb += 16) {
        // Prefetch next tile into the other buffer (no sync needed before
        // compute: writes go to buf^1, compute reads buf).
        if (kb + 16 < K) {
            int nb = buf ^ 1;
            float4 av0 = *(const float4*)(A + (size_t)(mbase + row0) * K + kb + 16 + seg0 * 4);
            float4 av1 = *(const float4*)(A + (size_t)(mbase + row1) * K + kb + 16 + seg1 * 4);
            float4 bv0 = *(const float4*)(Bw + (size_t)(nbase + row0) * K + kb + 16 + seg0 * 4);
            float4 bv1 = *(const float4*)(Bw + (size_t)(nbase + row1) * K + kb + 16 + seg1 * 4);
            As[nb][(seg0 * 4 + 0) * 128 + row0] = av0.x;
            As[nb][(seg0 * 4 + 1) * 128 + row0] = av0.y;
            As[nb][(seg0 * 4 + 2) * 128 + row0] = av0.z;
            As[nb][(seg0 * 4 + 3) * 128 + row0] = av0.w;
            As[nb][(seg1 * 4 + 0) * 128 + row1] = av1.x;
            As[nb][(seg1 * 4 + 1) * 128 + row1] = av1.y;
            As[nb][(seg1 * 4 + 2) * 128 + row1] = av1.z;
            As[nb][(seg1 * 4 + 3) * 128 + row1] = av1.w;
            Bs[nb][(seg0 * 4 + 0) * 128 + row0] = bv0.x;
            Bs[nb][(seg0 * 4 + 1) * 128 + row0] = bv0.y;
            Bs[nb][(seg0 * 4 + 2) * 128 + row0] = bv0.z;
            Bs[nb][(seg0 * 4 + 3) * 128 + row0] = bv0.w;
            Bs[nb][(seg1 * 4 + 0) * 128 + row1] = bv1.x;
            Bs[nb][(seg1 * 4 + 1) * 128 + row1] = bv1.y;
            Bs[nb][(seg1 * 4 + 2) * 128 + row1] = bv1.z;
            Bs[nb][(seg1 * 4 + 3) * 128 + row1] = bv1.w;
        }
#pragma unroll
        for (int kk = 0; kk < 16; kk++) {
            float4 a0 = *(float4*)&As[buf][kk * 128 + ty * 8];
            float4 a1 = *(float4*)&As[buf][kk * 128 + ty * 8 + 4];
            float4 b0 = *(float4*)&Bs[buf][kk * 128 + tx * 8];
            float4 b1 = *(float4*)&Bs[buf][kk * 128 + tx * 8 + 4];
            float a[8] = {a0.x, a0.y, a0.z, a0.w, a1.x, a1.y, a1.z, a1.w};
            float bb[8] = {b0.x, b0.y, b0.z, b0.w, b1.x, b1.y, b1.z, b1.w};
#pragma unroll
            for (int i = 0; i < 8; i++)
#pragma unroll
                for (int j = 0; j < 8; j++)
                    acc[i][j] = fmaf(a[i], bb[j], acc[i][j]);
        }
        __syncthreads();   // writes to buf^1 done by all; reads of buf done
        buf ^= 1;
    }

#pragma unroll
    for (int i = 0; i < 8; i++) {
        float* dst = C + (size_t)(mbase + ty * 8 + i) * N + nbase + tx * 8;
        float4 o0 = {acc[i][0], acc[i][1], acc[i][2], acc[i][3]};
        float4 o1 = {acc[i][4], acc[i][5], acc[i][6], acc[i][7]};
        *(float4*)dst = o0;
        *(float4*)(dst + 4) = o1;
    }
}

// ---------------------------------------------------------------------------
// Kernel 4: fused attention. Block = (b,h) x 128-row q tile, full hd=128.
// force = min(m_q*m_k*recip, 50); P = exp(force) (no max pass needed:
// force bounded in (0,50]); head_out = (P @ V_h) / rowsum(P).
// 256 threads, 8x8 micro-tile over (q, hd); k tiled by 32.
// ---------------------------------------------------------------------------
__global__ __launch_bounds__(256) void k_attn() {
    __shared__ float p_s[128 * 32];   // [q][kk]
    __shared__ float v_s[32 * 128];   // [kk][c]
    __shared__ float mq_s[128];
    __shared__ float den_s[128];

    int tid = threadIdx.x;
    int tx = tid & 15, ty = tid >> 4;
    int w = tid >> 5, lane = tid & 31;
    int bh = blockIdx.y;              // 0..15
    int b = bh >> 3, h = bh & 7;
    int qbase = blockIdx.x * 128;

    const float* mass = g_masses + (size_t)bh * SB;
    const float* vbase = g_v + (size_t)b * SB * DD + h * HD;

    if (tid < 128) mq_s[tid] = mass[qbase + tid];

    float acc[8][8];
#pragma unroll
    for (int i = 0; i < 8; i++)
#pragma unroll
        for (int j = 0; j < 8; j++) acc[i][j] = 0.f;
    float dpart[16];
#pragma unroll
    for (int r = 0; r < 16; r++) dpart[r] = 0.f;

    for (int kb = 0; kb < SB; kb += 32) {
        __syncthreads();
        // stage V tile: 32 x 128 floats = 1024 float4s, 4 per thread
#pragma unroll
        for (int r = 0; r < 4; r++) {
            int i4 = r * 256 + tid;
            int kk = i4 >> 5, c4 = i4 & 31;
            float4 vv = *(const float4*)(vbase + (size_t)(kb + kk) * DD + c4 * 4);
            *(float4*)&v_s[kk * 128 + c4 * 4] = vv;
        }
        // stage P tile: 128 x 32 = 4096, 16 per thread; fixed kk per thread
        int kkc = tid & 31;
        float mk = __ldg(mass + kb + kkc);
#pragma unroll
        for (int r = 0; r < 16; r++) {
            int qq = r * 8 + (tid >> 5);
            float rec = g_recip[(size_t)(qbase + qq) * SB + kb + kkc];
            float f = fminf(mq_s[qq] * mk * rec, 50.0f);
            float ev = fast_exp_pos(f);
            p_s[qq * 32 + kkc] = ev;
            dpart[r] += ev;
        }
        __syncthreads();
#pragma unroll
        for (int kk = 0; kk < 32; kk++) {
            float a[8];
#pragma unroll
            for (int i = 0; i < 8; i++) a[i] = p_s[(ty * 8 + i) * 32 + kk];
            float4 b0 = *(float4*)&v_s[kk * 128 + tx * 8];
            float4 b1 = *(float4*)&v_s[kk * 128 + tx * 8 + 4];
            float bb[8] = {b0.x, b0.y, b0.z, b0.w, b1.x, b1.y, b1.z, b1.w};
#pragma unroll
            for (int i = 0; i < 8; i++)
#pragma unroll
                for (int j = 0; j < 8; j++)
                    acc[i][j] = fmaf(a[i], bb[j], acc[i][j]);
        }
    }

    // Row-sum reduce: for iter r, all 32 lanes of warp w hold partials of the
    // SAME q row (q = 8r + w), each over a distinct kk column class.
#pragma unroll
    for (int r = 0; r < 16; r++) {
        float d = dpart[r];
#pragma unroll
        for (int o = 16; o; o >>= 1) d += __shfl_xor_sync(0xffffffffu, d, o);
        if (lane == 0) den_s[r * 8 + w] = d;
    }
    __syncthreads();

#pragma unroll
    for (int i = 0; i < 8; i++) {
        float inv = 1.0f / den_s[ty * 8 + i];
        float* dst = g_ho + ((size_t)b * SB + qbase + ty * 8 + i) * DD + h * HD + tx * 8;
        float4 o0 = {acc[i][0] * inv, acc[i][1] * inv, acc[i][2] * inv, acc[i][3] * inv};
        float4 o1 = {acc[i][4] * inv, acc[i][5] * inv, acc[i][6] * inv, acc[i][7] * inv};
        *(float4*)dst = o0;
        *(float4*)(dst + 4) = o1;
    }
}

// ---------------------------------------------------------------------------
extern "C" void kernel_launch(void* const* d_in, const int* in_sizes, int n_in,
                              void* d_out, int out_size) {
    const float* x      = (const float*)d_in[0];
    const float* mass_w = (const float*)d_in[1];
    const float* v_w    = (const float*)d_in[2];
    const float* out_w  = (const float*)d_in[3];
    const float* pos    = (const float*)d_in[4];
    float* out = (float*)d_out;

    k_recip<<<(SB * SB) / 256, 256>>>(pos);
    k_masses<<<(BB * HH * SB) / 8, 256>>>(x, mass_w);
    k_gemm_nt<<<dim3(DD / 128, (BB * SB) / 128), 256>>>(x, v_w, nullptr, 0);
    k_attn<<<dim3(SB / 128, BB * HH), 256>>>();
    k_gemm_nt<<<dim3(DD / 128, (BB * SB) / 128), 256>>>(nullptr, out_w, out, 1);
}

// round 3
// speedup vs baseline: 1.1102x; 1.1102x over previous
#include <cuda_runtime.h>
#include <math.h>

// Shapes are fixed by the dataset.
#define SB 2048
#define BB 2
#define HH 8
#define HD 128
#define DD 1024

// Scratch (static device globals: allowed; no runtime allocation).
__device__ float g_recip[(size_t)SB * SB];        // 16 MB: 1/(dist^2 + eps)
__device__ float g_masses[BB * HH * SB];          // (b,h,s)
__device__ float g_v[(size_t)BB * SB * DD];       // v = x @ v_w^T, (B,S,D)
__device__ float g_ho[(size_t)BB * SB * DD];      // head_out, (B,S,D)

// FMA-only exp for f in [0, 50]. Avoids MUFU throughput wall (67M exps).
__device__ __forceinline__ float fast_exp_pos(float f) {
    float t = f * 1.44269504088896340736f;
    float z = t + 12582912.0f;            // round-to-nearest int (n in [0,73])
    float n = z - 12582912.0f;
    float r = t - n;
    float p = 1.5403530e-4f;
    p = fmaf(p, r, 1.3333558e-3f);
    p = fmaf(p, r, 9.6181291e-3f);
    p = fmaf(p, r, 5.5504109e-2f);
    p = fmaf(p, r, 2.4022651e-1f);
    p = fmaf(p, r, 6.9314718e-1f);
    p = fmaf(p, r, 1.0f);
    int e = (int)n;
    return p * __int_as_float((e + 127) << 23);
}

// ---------------------------------------------------------------------------
// Kernel 1: recip[q,k] = 1 / (dist(q,k)^2 + 1e-6), warped distance.
// ---------------------------------------------------------------------------
__global__ void k_recip(const float* __restrict__ pos) {
    int idx = blockIdx.x * blockDim.x + threadIdx.x;   // S*S = 4M threads
    int q = idx >> 11;
    int k = idx & (SB - 1);
    float4 q0 = *(const float4*)(pos + q * 8);
    float4 q1 = *(const float4*)(pos + q * 8 + 4);
    float4 k0 = *(const float4*)(pos + k * 8);
    float4 k1 = *(const float4*)(pos + k * 8 + 4);
    float d2 = 1e-12f;
    float df;
    df = q0.x - k0.x; d2 = fmaf(df, df, d2);
    df = q0.y - k0.y; d2 = fmaf(df, df, d2);
    df = q0.z - k0.z; d2 = fmaf(df, df, d2);
    df = q0.w - k0.w; d2 = fmaf(df, df, d2);
    df = q1.x - k1.x; d2 = fmaf(df, df, d2);
    df = q1.y - k1.y; d2 = fmaf(df, df, d2);
    df = q1.z - k1.z; d2 = fmaf(df, df, d2);
    df = q1.w - k1.w; d2 = fmaf(df, df, d2);
    float dist = sqrtf(d2);
    dist = dist * (1.0f + 0.15f * __sinf(dist));   // |x| <= ~12, MUFU.SIN fine
    dist = fmaxf(dist, 0.0f);
    g_recip[idx] = __fdividef(1.0f, fmaf(dist, dist, 1e-6f));
}

// ---------------------------------------------------------------------------
// Kernel 2: masses[b,h,s] = sigmoid(dot(x[b,s,h*128:+128], mass_w[h])).
// ---------------------------------------------------------------------------
__global__ void k_masses(const float* __restrict__ x, const float* __restrict__ mw) {
    int g = blockIdx.x * 8 + (threadIdx.x >> 5);   // 0 .. B*H*S-1
    int lane = threadIdx.x & 31;
    int b = g >> 14;          // H*S = 16384
    int h = (g >> 11) & 7;
    int s = g & 2047;
    const float* xr = x + ((size_t)b * SB + s) * DD + h * HD;
    const float* wr = mw + h * HD;
    float sum = 0.f;
#pragma unroll
    for (int i = 0; i < 4; i++)
        sum = fmaf(xr[lane + 32 * i], wr[lane + 32 * i], sum);
#pragma unroll
    for (int o = 16; o; o >>= 1)
        sum += __shfl_xor_sync(0xffffffffu, sum, o);
    if (lane == 0)
        g_masses[g] = 1.0f / (1.0f + __expf(-sum));
}

// ---------------------------------------------------------------------------
// Kernels 3 & 5: C[m,n] = sum_k A[m,k] * Bw[n,k]  (NT GEMM, all row-major).
// M=4096, N=K=1024. 128x128 tile, 256 threads, 8x8 micro-tile.
// Reg-staged double buffer: LDG (next tile) issued BEFORE compute, STS after
// — global-load latency hidden behind the 1024-FMA tile loop.
// ---------------------------------------------------------------------------
__global__ __launch_bounds__(256) void k_gemm_nt(const float* __restrict__ Ain,
                                                 const float* __restrict__ Bw,
                                                 float* __restrict__ Cext,
                                                 int mode) {
    const float* A = (mode == 0) ? Ain : g_ho;
    float* C = (mode == 0) ? g_v : Cext;
    const int K = DD, N = DD;

    __shared__ float As[2][16 * 128];   // [buf][kk][m]
    __shared__ float Bs[2][16 * 128];   // [buf][kk][n]

    int tid = threadIdx.x;
    int tx = tid & 15, ty = tid >> 4;
    int mbase = blockIdx.y * 128, nbase = blockIdx.x * 128;

    // Per-thread load coords: 512 float4s per operand per tile, 2 per thread.
    int row0 = (tid * 2) >> 2, seg0 = (tid * 2) & 3;
    int row1 = (tid * 2 + 1) >> 2, seg1 = (tid * 2 + 1) & 3;
    const float* pa0 = A + (size_t)(mbase + row0) * K + seg0 * 4;
    const float* pa1 = A + (size_t)(mbase + row1) * K + seg1 * 4;
    const float* pb0 = Bw + (size_t)(nbase + row0) * K + seg0 * 4;
    const float* pb1 = Bw + (size_t)(nbase + row1) * K + seg1 * 4;

    float acc[8][8];
#pragma unroll
    for (int i = 0; i < 8; i++)
#pragma unroll
        for (int j = 0; j < 8; j++) acc[i][j] = 0.f;

    float4 av0, av1, bv0, bv1;

    // Prologue: tile 0 -> regs -> buf 0.
    av0 = *(const float4*)(pa0);
    av1 = *(const float4*)(pa1);
    bv0 = *(const float4*)(pb0);
    bv1 = *(const float4*)(pb1);
    {
        As[0][(seg0 * 4 + 0) * 128 + row0] = av0.x;
        As[0][(seg0 * 4 + 1) * 128 + row0] = av0.y;
        As[0][(seg0 * 4 + 2) * 128 + row0] = av0.z;
        As[0][(seg0 * 4 + 3) * 128 + row0] = av0.w;
        As[0][(seg1 * 4 + 0) * 128 + row1] = av1.x;
        As[0][(seg1 * 4 + 1) * 128 + row1] = av1.y;
        As[0][(seg1 * 4 + 2) * 128 + row1] = av1.z;
        As[0][(seg1 * 4 + 3) * 128 + row1] = av1.w;
        Bs[0][(seg0 * 4 + 0) * 128 + row0] = bv0.x;
        Bs[0][(seg0 * 4 + 1) * 128 + row0] = bv0.y;
        Bs[0][(seg0 * 4 + 2) * 128 + row0] = bv0.z;
        Bs[0][(seg0 * 4 + 3) * 128 + row0] = bv0.w;
        Bs[0][(seg1 * 4 + 0) * 128 + row1] = bv1.x;
        Bs[0][(seg1 * 4 + 1) * 128 + row1] = bv1.y;
        Bs[0][(seg1 * 4 + 2) * 128 + row1] = bv1.z;
        Bs[0][(seg1 * 4 + 3) * 128 + row1] = bv1.w;
    }
    __syncthreads();

    int buf = 0;
    for (int kb = 0; kb < K; kb += 16) {
        bool more = (kb + 16 < K);
        if (more) {                     // issue LDGs early; consume after compute
            av0 = *(const float4*)(pa0 + kb + 16);
            av1 = *(const float4*)(pa1 + kb + 16);
            bv0 = *(const float4*)(pb0 + kb + 16);
            bv1 = *(const float4*)(pb1 + kb + 16);
        }
#pragma unroll
        for (int kk = 0; kk < 16; kk++) {
            float4 a0 = *(float4*)&As[buf][kk * 128 + ty * 8];
            float4 a1 = *(float4*)&As[buf][kk * 128 + ty * 8 + 4];
            float4 b0 = *(float4*)&Bs[buf][kk * 128 + tx * 8];
            float4 b1 = *(float4*)&Bs[buf][kk * 128 + tx * 8 + 4];
            float a[8] = {a0.x, a0.y, a0.z, a0.w, a1.x, a1.y, a1.z, a1.w};
            float bb[8] = {b0.x, b0.y, b0.z, b0.w, b1.x, b1.y, b1.z, b1.w};
#pragma unroll
            for (int i = 0; i < 8; i++)
#pragma unroll
                for (int j = 0; j < 8; j++)
                    acc[i][j] = fmaf(a[i], bb[j], acc[i][j]);
        }
        if (more) {
            int nb = buf ^ 1;
            As[nb][(seg0 * 4 + 0) * 128 + row0] = av0.x;
            As[nb][(seg0 * 4 + 1) * 128 + row0] = av0.y;
            As[nb][(seg0 * 4 + 2) * 128 + row0] = av0.z;
            As[nb][(seg0 * 4 + 3) * 128 + row0] = av0.w;
            As[nb][(seg1 * 4 + 0) * 128 + row1] = av1.x;
            As[nb][(seg1 * 4 + 1) * 128 + row1] = av1.y;
            As[nb][(seg1 * 4 + 2) * 128 + row1] = av1.z;
            As[nb][(seg1 * 4 + 3) * 128 + row1] = av1.w;
            Bs[nb][(seg0 * 4 + 0) * 128 + row0] = bv0.x;
            Bs[nb][(seg0 * 4 + 1) * 128 + row0] = bv0.y;
            Bs[nb][(seg0 * 4 + 2) * 128 + row0] = bv0.z;
            Bs[nb][(seg0 * 4 + 3) * 128 + row0] = bv0.w;
            Bs[nb][(seg1 * 4 + 0) * 128 + row1] = bv1.x;
            Bs[nb][(seg1 * 4 + 1) * 128 + row1] = bv1.y;
            Bs[nb][(seg1 * 4 + 2) * 128 + row1] = bv1.z;
            Bs[nb][(seg1 * 4 + 3) * 128 + row1] = bv1.w;
        }
        __syncthreads();
        buf ^= 1;
    }

#pragma unroll
    for (int i = 0; i < 8; i++) {
        float* dst = C + (size_t)(mbase + ty * 8 + i) * N + nbase + tx * 8;
        float4 o0 = {acc[i][0], acc[i][1], acc[i][2], acc[i][3]};
        float4 o1 = {acc[i][4], acc[i][5], acc[i][6], acc[i][7]};
        *(float4*)dst = o0;
        *(float4*)(dst + 4) = o1;
    }
}

// ---------------------------------------------------------------------------
// Kernel 4: fused attention, software-pipelined.
// Per 32-k tile: [regs hold tile data] -> store V + exp(P) to smem -> sync
// -> issue LDG prefetch of next tile into regs -> 2048-FMA PV loop (hides
// prefetch latency) -> sync. p_s padded stride 33 (bank-conflict-free).
// ---------------------------------------------------------------------------
#define PSTRIDE 33
__global__ __launch_bounds__(256) void k_attn() {
    __shared__ float p_s[128 * PSTRIDE];   // [q][kk], padded
    __shared__ float v_s[32 * 128];        // [kk][c]
    __shared__ float mq_s[128];
    __shared__ float den_s[128];

    int tid = threadIdx.x;
    int tx = tid & 15, ty = tid >> 4;
    int w = tid >> 5, lane = tid & 31;
    int bh = blockIdx.y;              // 0..15
    int b = bh >> 3, h = bh & 7;
    int qbase = blockIdx.x * 128;

    const float* mass = g_masses + (size_t)bh * SB;
    const float* vbase = g_v + (size_t)b * SB * DD + h * HD;
    const float* recbase = g_recip + (size_t)qbase * SB;

    if (tid < 128) mq_s[tid] = mass[qbase + tid];
    __syncthreads();

    float acc[8][8];
#pragma unroll
    for (int i = 0; i < 8; i++)
#pragma unroll
        for (int j = 0; j < 8; j++) acc[i][j] = 0.f;
    float dpart[16];
#pragma unroll
    for (int r = 0; r < 16; r++) dpart[r] = 0.f;

    // V-prefetch coords: 4 float4 per thread (tile is 32x128 = 1024 float4).
    int vk[4], vc[4];
#pragma unroll
    for (int r = 0; r < 4; r++) {
        int i4 = r * 256 + tid;
        vk[r] = i4 >> 5;
        vc[r] = i4 & 31;
    }
    int kkc = tid & 31;               // this thread's fixed k column
    int qrow = tid >> 5;              // q row class (0..7)

    float4 vreg[4];
    float rec[16];
    float mk;

    // Prologue: prefetch tile kb=0 into registers.
#pragma unroll
    for (int r = 0; r < 4; r++)
        vreg[r] = *(const float4*)(vbase + (size_t)vk[r] * DD + vc[r] * 4);
    mk = __ldg(mass + kkc);
#pragma unroll
    for (int r = 0; r < 16; r++)
        rec[r] = recbase[(size_t)(r * 8 + qrow) * SB + kkc];

    for (int kb = 0; kb < SB; kb += 32) {
        // Stage regs -> smem (V tile + exp'd P tile).
#pragma unroll
        for (int r = 0; r < 4; r++)
            *(float4*)&v_s[vk[r] * 128 + vc[r] * 4] = vreg[r];
        float mqv;
#pragma unroll
        for (int r = 0; r < 16; r++) {
            int qq = r * 8 + qrow;
            mqv = mq_s[qq];
            float f = fminf(mqv * mk * rec[r], 50.0f);
            float ev = fast_exp_pos(f);
            p_s[qq * PSTRIDE + kkc] = ev;
            dpart[r] += ev;
        }
        __syncthreads();

        // Prefetch next tile into regs; latency hidden by the PV loop below.
        if (kb + 32 < SB) {
            const float* vnext = vbase + (size_t)(kb + 32) * DD;
#pragma unroll
            for (int r = 0; r < 4; r++)
                vreg[r] = *(const float4*)(vnext + (size_t)vk[r] * DD + vc[r] * 4);
            mk = __ldg(mass + kb + 32 + kkc);
            const float* rnext = recbase + kb + 32;
#pragma unroll
            for (int r = 0; r < 16; r++)
                rec[r] = rnext[(size_t)(r * 8 + qrow) * SB + kkc];
        }

        // PV: 32 kk x 8x8 FMAs.
#pragma unroll
        for (int kk = 0; kk < 32; kk++) {
            float a[8];
#pragma unroll
            for (int i = 0; i < 8; i++) a[i] = p_s[(ty * 8 + i) * PSTRIDE + kk];
            float4 b0 = *(float4*)&v_s[kk * 128 + tx * 8];
            float4 b1 = *(float4*)&v_s[kk * 128 + tx * 8 + 4];
            float bb[8] = {b0.x, b0.y, b0.z, b0.w, b1.x, b1.y, b1.z, b1.w};
#pragma unroll
            for (int i = 0; i < 8; i++)
#pragma unroll
                for (int j = 0; j < 8; j++)
                    acc[i][j] = fmaf(a[i], bb[j], acc[i][j]);
        }
        __syncthreads();
    }

    // Row-sum reduce: for iter r, all 32 lanes of warp w hold partials of the
    // SAME q row (q = 8r + w), each over a distinct kk column class.
#pragma unroll
    for (int r = 0; r < 16; r++) {
        float d = dpart[r];
#pragma unroll
        for (int o = 16; o; o >>= 1) d += __shfl_xor_sync(0xffffffffu, d, o);
        if (lane == 0) den_s[r * 8 + w] = d;
    }
    __syncthreads();

#pragma unroll
    for (int i = 0; i < 8; i++) {
        float inv = 1.0f / den_s[ty * 8 + i];
        float* dst = g_ho + ((size_t)b * SB + qbase + ty * 8 + i) * DD + h * HD + tx * 8;
        float4 o0 = {acc[i][0] * inv, acc[i][1] * inv, acc[i][2] * inv, acc[i][3] * inv};
        float4 o1 = {acc[i][4] * inv, acc[i][5] * inv, acc[i][6] * inv, acc[i][7] * inv};
        *(float4*)dst = o0;
        *(float4*)(dst + 4) = o1;
    }
}

// ---------------------------------------------------------------------------
extern "C" void kernel_launch(void* const* d_in, const int* in_sizes, int n_in,
                              void* d_out, int out_size) {
    const float* x      = (const float*)d_in[0];
    const float* mass_w = (const float*)d_in[1];
    const float* v_w    = (const float*)d_in[2];
    const float* out_w  = (const float*)d_in[3];
    const float* pos    = (const float*)d_in[4];
    float* out = (float*)d_out;

    k_recip<<<(SB * SB) / 256, 256>>>(pos);
    k_masses<<<(BB * HH * SB) / 8, 256>>>(x, mass_w);
    k_gemm_nt<<<dim3(DD / 128, (BB * SB) / 128), 256>>>(x, v_w, nullptr, 0);
    k_attn<<<dim3(SB / 128, BB * HH), 256>>>();
    k_gemm_nt<<<dim3(DD / 128, (BB * SB) / 128), 256>>>(nullptr, out_w, out, 1);
}